// round 4
// baseline (speedup 1.0000x reference)
#include <cuda_runtime.h>
#include <cuda_bf16.h>
#include <math.h>
#include <stdint.h>
#include <stddef.h>

#define TT 64
#define BB 512
#define FF 72
#define HH 1024
#define G4 4096
#define BLK 8192                 // elements per 128x64 bf16 tile (16KB)
#define NSTAGE 4
#define STAGE_BYTES 32768        // A tile 16KB + B tile 16KB
#define SMEM_BYTES (NSTAGE * STAGE_BYTES + 1024)

// ---------------------------------------------------------------------------
// Scratch (device globals; allocations are forbidden)
// ---------------------------------------------------------------------------
struct __align__(16) Scratch {
    float bias0[G4], bias1[G4];
    float c0[HH * BB], c1[HH * BB];           // transposed: [unit][batch]
    float h1t[HH * BB];                       // fresh fp32 h1, transposed, for linear
    float fb[BB * FF];                        // feedback accumulator fp32
    __nv_bfloat16 xg[(TT - 1) * 4 * 2 * BLK]; // [t][m][2][BLK] swizzled
    __nv_bfloat16 W0[32 * 18 * BLK];          // [j][18][BLK] gate-interleaved rows
    __nv_bfloat16 W1[32 * 32 * BLK];
    __nv_bfloat16 h0s[2][4 * 16 * BLK];       // ping-pong state, swizzled
    __nv_bfloat16 h1s[2][4 * 16 * BLK];
    __nv_bfloat16 h0n[2][4 * 16 * BLK];       // fresh layer0 out, double-buffered
    __nv_bfloat16 fbt[4 * 2 * BLK];           // feedback, swizzled, padded
};
__device__ Scratch g_scratch;

// ---------------------------------------------------------------------------
// Helpers
// ---------------------------------------------------------------------------
__device__ __forceinline__ int swb(int byte) { return byte ^ ((byte >> 3) & 0x70); }
__device__ __forceinline__ int swofs(int r, int k) { return swb(r * 128 + k * 2) >> 1; }
__device__ __forceinline__ float sigmoidf_(float x) { return 1.0f / (1.0f + expf(-x)); }
__device__ __forceinline__ void cp16(uint32_t saddr, const void* gaddr) {
    asm volatile("cp.async.cg.shared.global [%0], [%1], 16;\n" :: "r"(saddr), "l"(gaddr));
}
__device__ __forceinline__ uint32_t smem_u32(const void* p) {
    return (uint32_t)__cvta_generic_to_shared(p);
}
__device__ __forceinline__ void ldsm4(uint32_t* r, uint32_t addr) {
    asm volatile("ldmatrix.sync.aligned.m8n8.x4.shared.b16 {%0,%1,%2,%3}, [%4];"
                 : "=r"(r[0]), "=r"(r[1]), "=r"(r[2]), "=r"(r[3]) : "r"(addr));
}
__device__ __forceinline__ void mma_bf16(float* c, const uint32_t* a, const uint32_t* b) {
    asm volatile(
        "mma.sync.aligned.m16n8k16.row.col.f32.bf16.bf16.f32 "
        "{%0,%1,%2,%3},{%4,%5,%6,%7},{%8,%9},{%0,%1,%2,%3};\n"
        : "+f"(c[0]), "+f"(c[1]), "+f"(c[2]), "+f"(c[3])
        : "r"(a[0]), "r"(a[1]), "r"(a[2]), "r"(a[3]), "r"(b[0]), "r"(b[1]));
}

// ---------------------------------------------------------------------------
// GEMM descriptor
// ---------------------------------------------------------------------------
struct GemmArgs {
    const __nv_bfloat16 *Aa, *Ab, *W;
    int Ca, Cb;
    const float* bias;
    const __nv_bfloat16* h_read;
    __nv_bfloat16* h_write;
    float* cbuf;                 // [unit][batch]
    __nv_bfloat16* hn_sw;        // fresh h, swizzled (nullable)
    float* hn_f32;               // fresh h, transposed fp32 (nullable)
    const int* lengths;
    int t, masked;
};

// ---------------------------------------------------------------------------
// Setup kernel 1: zero states + normalize/swizzle encoder inputs
// ---------------------------------------------------------------------------
__global__ void setup1_kernel(const float* __restrict__ u, const float* __restrict__ mean,
                              const float* __restrict__ stdv) {
    Scratch* S = &g_scratch;
    const int stride = gridDim.x * blockDim.x;
    const int t0 = blockIdx.x * blockDim.x + threadIdx.x;
    const __nv_bfloat16 z = __float2bfloat16(0.0f);
    for (int i = t0; i < 4 * 16 * BLK; i += stride) { S->h0s[0][i] = z; S->h1s[0][i] = z; }
    for (int i = t0; i < HH * BB; i += stride) { S->c0[i] = 0.0f; S->c1[i] = 0.0f; }
    for (int idx = t0; idx < (TT - 1) * 8 * BLK; idx += stride) {
        int e = idx & (BLK - 1);
        int i = (idx >> 13) & 1, m = (idx >> 14) & 3, t = idx >> 16;
        int r = e >> 6, k = e & 63;
        int b = m * 128 + r, col = i * 64 + k;
        float v = (col < FF) ? (u[((size_t)t * BB + b) * FF + col] - mean[col]) / stdv[col]
                             : 0.0f;
        S->xg[(size_t)(idx >> 13) * BLK + swofs(r, k)] = __float2bfloat16(v);
    }
}

// ---------------------------------------------------------------------------
// Setup kernel 2: weights (gate-interleaved SW128 tiles), biases, feedback init
// ---------------------------------------------------------------------------
__global__ void setup2_kernel(const float* __restrict__ u, const float* __restrict__ mean,
                              const float* __restrict__ stdv, const int* __restrict__ lengths,
                              const float* __restrict__ Wih0, const float* __restrict__ Whh0,
                              const float* __restrict__ Wih1, const float* __restrict__ Whh1,
                              const float* __restrict__ bi0, const float* __restrict__ bh0,
                              const float* __restrict__ bi1, const float* __restrict__ bh1) {
    Scratch* S = &g_scratch;
    const int stride = gridDim.x * blockDim.x;
    const int t0 = blockIdx.x * blockDim.x + threadIdx.x;
    // W0: 18 chunks (2 input-pad + 16 hh), gate-interleaved tile rows
    for (int idx = t0; idx < 32 * 18 * BLK; idx += stride) {
        int e = idx & (BLK - 1);
        int blk = idx >> 13;
        int i = blk % 18, j = blk / 18;
        int r = e >> 6, k = e & 63;
        int n = (r & 3) * 1024 + j * 32 + (r >> 2);
        float v;
        if (i < 2) {
            int col = i * 64 + k;
            v = (col < FF) ? Wih0[(size_t)n * FF + col] : 0.0f;
        } else {
            v = Whh0[(size_t)n * HH + (i - 2) * 64 + k];
        }
        S->W0[(size_t)blk * BLK + swofs(r, k)] = __float2bfloat16(v);
    }
    // W1: 32 chunks (16 ih + 16 hh)
    for (int idx = t0; idx < 32 * 32 * BLK; idx += stride) {
        int e = idx & (BLK - 1);
        int blk = idx >> 13;
        int i = blk & 31, j = blk >> 5;
        int r = e >> 6, k = e & 63;
        int n = (r & 3) * 1024 + j * 32 + (r >> 2);
        float v = (i < 16) ? Wih1[(size_t)n * HH + i * 64 + k]
                           : Whh1[(size_t)n * HH + (i - 16) * 64 + k];
        S->W1[(size_t)blk * BLK + swofs(r, k)] = __float2bfloat16(v);
    }
    for (int i = t0; i < G4; i += stride) {
        S->bias0[i] = bi0[i] + bh0[i];
        S->bias1[i] = bi1[i] + bh1[i];
    }
    // feedback = batch[lengths-1] (normalized); fp32 + swizzled bf16
    for (int idx = t0; idx < 4 * 2 * BLK; idx += stride) {
        int e = idx & (BLK - 1);
        int i = (idx >> 13) & 1, m = idx >> 14;
        int r = e >> 6, k = e & 63;
        int b = m * 128 + r, col = i * 64 + k;
        int tt = lengths[b] - 1;
        float v = (col < FF) ? (u[((size_t)tt * BB + b) * FF + col] - mean[col]) / stdv[col]
                             : 0.0f;
        S->fbt[(size_t)(idx >> 13) * BLK + swofs(r, k)] = __float2bfloat16(v);
    }
    for (int idx = t0; idx < BB * FF; idx += stride) {
        int b = idx / FF, n = idx % FF;
        int tt = lengths[b] - 1;
        S->fb[idx] = (u[((size_t)tt * BB + b) * FF + n] - mean[n]) / stdv[n];
    }
}

// ---------------------------------------------------------------------------
// Unified GEMM(+GEMM) + register LSTM epilogue kernel.
// CTA tile: 128 batch x 128 gate-interleaved cols (32 units x 4 gates).
// 8 warps = 4 M x 2 N. Continuous cp.async pipeline across both GEMMs.
// ---------------------------------------------------------------------------
__global__ void __launch_bounds__(256) lstm2_kernel(GemmArgs g1, GemmArgs g2, int has2) {
    extern __shared__ char raw_sm[];
    char* dsm = (char*)(((uintptr_t)raw_sm + 1023) & ~(uintptr_t)1023);
    const uint32_t dsm32 = smem_u32(dsm);

    const int tid = threadIdx.x;
    const int w = tid >> 5, lane = tid & 31;
    const int wm = w & 3, wn = w >> 2;
    const int tig = lane & 3;
    const int bx = blockIdx.x, by = blockIdx.y;
    const int m0 = bx * 128, u0 = by * 32;
    const int CT1 = g1.Ca + g1.Cb;
    const int CT2 = has2 ? (g2.Ca + g2.Cb) : 0;
    const int CT = CT1 + CT2;

    const __nv_bfloat16* A1a = g1.Aa + (size_t)bx * g1.Ca * BLK;
    const __nv_bfloat16* A1b = g1.Ab + (size_t)bx * g1.Cb * BLK;
    const __nv_bfloat16* W1m = g1.W + (size_t)by * CT1 * BLK;
    const __nv_bfloat16* A2a = g2.Aa + (size_t)bx * g2.Ca * BLK;
    const __nv_bfloat16* A2b = g2.Ab + (size_t)bx * g2.Cb * BLK;
    const __nv_bfloat16* W2m = g2.W + (size_t)by * (g2.Ca + g2.Cb) * BLK;

    // ldmatrix lane patterns (tile-relative, pre-swizzle)
    const int rowA = wm * 32 + (lane & 15);
    const int cbA = (lane >> 4) * 16;
    const int rowB = wn * 64 + (lane & 7) + ((lane >> 4) & 1) * 8;
    const int cbB = ((lane >> 3) & 1) * 16;

    float acc[2][8][4];
#pragma unroll
    for (int a = 0; a < 2; a++)
#pragma unroll
        for (int b = 0; b < 8; b++)
#pragma unroll
            for (int c = 0; c < 4; c++) acc[a][b][c] = 0.0f;

    auto issue_chunk = [&](int j, int s) {
        const char* as;
        const char* ws;
        if (j < CT1) {
            as = (const char*)((j < g1.Ca) ? (A1a + (size_t)j * BLK)
                                           : (A1b + (size_t)(j - g1.Ca) * BLK));
            ws = (const char*)(W1m + (size_t)j * BLK);
        } else {
            int j2 = j - CT1;
            as = (const char*)((j2 < g2.Ca) ? (A2a + (size_t)j2 * BLK)
                                            : (A2b + (size_t)(j2 - g2.Ca) * BLK));
            ws = (const char*)(W2m + (size_t)j2 * BLK);
        }
        uint32_t da = dsm32 + s * STAGE_BYTES + tid * 16;
#pragma unroll
        for (int r = 0; r < 4; r++) cp16(da + r * 4096, as + tid * 16 + r * 4096);
        uint32_t db = da + 16384;
#pragma unroll
        for (int r = 0; r < 4; r++) cp16(db + r * 4096, ws + tid * 16 + r * 4096);
        asm volatile("cp.async.commit_group;\n" ::);
    };

    // register epilogue: one (batch,unit) cell per lane per (mt,nt)
    auto epilogue = [&](const GemmArgs& g) {
#pragma unroll
        for (int mt = 0; mt < 2; mt++)
#pragma unroll
            for (int nt = 0; nt < 8; nt++) {
                float d0 = acc[mt][nt][0], d1 = acc[mt][nt][1];
                float d2 = acc[mt][nt][2], d3 = acc[mt][nt][3];
                float p0 = __shfl_xor_sync(0xffffffffu, d0, 1);
                float p1 = __shfl_xor_sync(0xffffffffu, d1, 1);
                float p2 = __shfl_xor_sync(0xffffffffu, d2, 1);
                float p3 = __shfl_xor_sync(0xffffffffu, d3, 1);
                acc[mt][nt][0] = 0.0f; acc[mt][nt][1] = 0.0f;
                acc[mt][nt][2] = 0.0f; acc[mt][nt][3] = 0.0f;
                int u = u0 + wn * 16 + 2 * nt + (tig >> 1);
                int b = m0 + wm * 32 + mt * 16 + (lane >> 2) + ((tig & 1) ? 8 : 0);
                float I, F, G, O;
                if (!(tig & 1)) { I = d0; F = d1; G = p0; O = p1; }
                else            { G = d2; O = d3; I = p2; F = p3; }
                I += g.bias[u]; F += g.bias[1024 + u];
                G += g.bias[2048 + u]; O += g.bias[3072 + u];
                float cp = g.cbuf[(size_t)u * BB + b];
                float cn = sigmoidf_(F) * cp + sigmoidf_(I) * tanhf(G);
                float hn = sigmoidf_(O) * tanhf(cn);
                __nv_bfloat16 hb = __float2bfloat16(hn);
                size_t hidx = (size_t)((b >> 7) * 16 + (u >> 6)) * BLK + swofs(b & 127, u & 63);
                bool upd = !g.masked || (g.t < g.lengths[b] - 1);
                if (upd) {
                    g.cbuf[(size_t)u * BB + b] = cn;
                    g.h_write[hidx] = hb;
                } else {
                    g.h_write[hidx] = g.h_read[hidx];
                }
                if (g.hn_sw) g.hn_sw[hidx] = hb;
                if (g.hn_f32) g.hn_f32[(size_t)u * BB + b] = hn;
            }
    };

#pragma unroll
    for (int j = 0; j < NSTAGE - 1; j++) issue_chunk(j, j);

    for (int i = 0; i < CT; i++) {
        const int s = i & (NSTAGE - 1);
        const int rem = CT - 1 - i;
        if (rem >= 2)      asm volatile("cp.async.wait_group 2;\n" ::);
        else if (rem == 1) asm volatile("cp.async.wait_group 1;\n" ::);
        else               asm volatile("cp.async.wait_group 0;\n" ::);
        __syncthreads();
        const int j = i + NSTAGE - 1;
        if (j < CT) issue_chunk(j, j & (NSTAGE - 1));

        const uint32_t Ab = dsm32 + s * STAGE_BYTES;
        const uint32_t Bb = Ab + 16384;
#pragma unroll
        for (int ks = 0; ks < 4; ks++) {
            uint32_t afr[2][4];
#pragma unroll
            for (int mt = 0; mt < 2; mt++)
                ldsm4(afr[mt], Ab + swb((rowA + mt * 16) * 128 + ks * 32 + cbA));
            uint32_t bfr[8][2];
#pragma unroll
            for (int pr = 0; pr < 4; pr++) {
                uint32_t r4[4];
                ldsm4(r4, Bb + swb((rowB + pr * 16) * 128 + ks * 32 + cbB));
                bfr[2 * pr][0] = r4[0]; bfr[2 * pr][1] = r4[1];
                bfr[2 * pr + 1][0] = r4[2]; bfr[2 * pr + 1][1] = r4[3];
            }
#pragma unroll
            for (int mt = 0; mt < 2; mt++)
#pragma unroll
                for (int nt = 0; nt < 8; nt++) mma_bf16(acc[mt][nt], afr[mt], bfr[nt]);
        }

        if (i == CT1 - 1) epilogue(g1);
        if (has2 && i == CT - 1) epilogue(g2);
    }
}

// ---------------------------------------------------------------------------
// Decoder linear readout: 8 batches per CTA, Wlin streamed once per CTA.
// h1t is [unit][batch] fp32.
// ---------------------------------------------------------------------------
__global__ void __launch_bounds__(256) linear_kernel(
    const float* __restrict__ h1t, const float* __restrict__ Wlin,
    const float* __restrict__ blin, const float* __restrict__ mean,
    const float* __restrict__ stdv, float* __restrict__ fb,
    __nv_bfloat16* __restrict__ fbt, float* __restrict__ out, int step) {
    __shared__ float hs[HH * 9];   // [u][8] padded to 9
    const int b0 = blockIdx.x * 8;
    const int tid = threadIdx.x;
    for (int idx = tid; idx < HH * 8; idx += 256) {
        int u = idx >> 3, bl = idx & 7;
        hs[u * 9 + bl] = h1t[(size_t)u * BB + b0 + bl];
    }
    __syncthreads();
    const int w = tid >> 5, lane = tid & 31;
#pragma unroll
    for (int jj = 0; jj < 9; jj++) {
        int n = w + 8 * jj;   // 0..71
        float a[8];
#pragma unroll
        for (int bl = 0; bl < 8; bl++) a[bl] = 0.0f;
        for (int u = lane; u < HH; u += 32) {
            float wv = Wlin[(size_t)n * HH + u];
#pragma unroll
            for (int bl = 0; bl < 8; bl++) a[bl] += wv * hs[u * 9 + bl];
        }
#pragma unroll
        for (int bl = 0; bl < 8; bl++)
#pragma unroll
            for (int off = 16; off; off >>= 1)
                a[bl] += __shfl_xor_sync(0xffffffffu, a[bl], off);
        if (lane == 0) {
#pragma unroll
            for (int bl = 0; bl < 8; bl++) {
                int b = b0 + bl;
                float f2 = fb[b * FF + n] + a[bl] + blin[n];
                fb[b * FF + n] = f2;
                fbt[(size_t)((b >> 7) * 2 + (n >> 6)) * BLK + swofs(b & 127, n & 63)] =
                    __float2bfloat16(f2);
                out[((size_t)step * BB + b) * FF + n] = f2 * stdv[n] + mean[n];
            }
        }
    }
}

// ---------------------------------------------------------------------------
// Host orchestration
// ---------------------------------------------------------------------------
extern "C" void kernel_launch(void* const* d_in, const int* in_sizes, int n_in,
                              void* d_out, int out_size) {
    int off = (n_in >= 15) ? 1 : 0;
    const float* batch_u = (const float*)d_in[0];
    const int* lengths   = (const int*)d_in[1];
    const float* mean    = (const float*)d_in[2 + off];
    const float* stdv    = (const float*)d_in[3 + off];
    const float* Wih0    = (const float*)d_in[4 + off];
    const float* Whh0    = (const float*)d_in[5 + off];
    const float* bih0    = (const float*)d_in[6 + off];
    const float* bhh0    = (const float*)d_in[7 + off];
    const float* Wih1    = (const float*)d_in[8 + off];
    const float* Whh1    = (const float*)d_in[9 + off];
    const float* bih1    = (const float*)d_in[10 + off];
    const float* bhh1    = (const float*)d_in[11 + off];
    const float* Wlin    = (const float*)d_in[12 + off];
    const float* blin    = (const float*)d_in[13 + off];
    float* out = (float*)d_out;
    const int OUTL = out_size / (BB * FF);

    Scratch* S = nullptr;
    cudaGetSymbolAddress((void**)&S, g_scratch);
    cudaFuncSetAttribute(lstm2_kernel, cudaFuncAttributeMaxDynamicSharedMemorySize,
                         SMEM_BYTES);

    // launches 1-2: setup (includes state zeroing + feedback init)
    setup1_kernel<<<1024, 256>>>(batch_u, mean, stdv);
    setup2_kernel<<<1024, 256>>>(batch_u, mean, stdv, lengths, Wih0, Whh0, Wih1, Whh1,
                                 bih0, bhh0, bih1, bhh1);

    dim3 grid(4, 32);
    int cur0 = 0, cur1 = 0, non = 0;

    auto L0args = [&](const __nv_bfloat16* Aa, int t, int masked) {
        GemmArgs g;
        g.Aa = Aa; g.Ca = 2; g.Ab = S->h0s[cur0]; g.Cb = 16;
        g.W = S->W0; g.bias = S->bias0;
        g.h_read = S->h0s[cur0]; g.h_write = S->h0s[cur0 ^ 1];
        g.cbuf = S->c0; g.hn_sw = S->h0n[non ^ 1]; g.hn_f32 = nullptr;
        g.lengths = lengths; g.t = t; g.masked = masked;
        return g;
    };
    auto L1args = [&](int t, int masked, float* hnf) {
        GemmArgs g;
        g.Aa = S->h0n[non]; g.Ca = 16; g.Ab = S->h1s[cur1]; g.Cb = 16;
        g.W = S->W1; g.bias = S->bias1;
        g.h_read = S->h1s[cur1]; g.h_write = S->h1s[cur1 ^ 1];
        g.cbuf = S->c1; g.hn_sw = nullptr; g.hn_f32 = hnf;
        g.lengths = lengths; g.t = t; g.masked = masked;
        return g;
    };

    // launch 3: E0 = layer0(t=0)  (h0n[non^1] gets t=0 output; flip non after)
    {
        GemmArgs g = L0args(S->xg, 0, 1);
        lstm2_kernel<<<grid, 256, SMEM_BYTES>>>(g, g, 0);
        cur0 ^= 1; non ^= 1;
    }
    // launches 4..66: merged K_t = layer1(t) + layer0(t+1)  (t=0..62)
    for (int t = 0; t < TT - 1; t++) {
        GemmArgs g1 = L1args(t, 1, nullptr);
        GemmArgs g2 = (t < TT - 2)
            ? L0args(S->xg + (size_t)(t + 1) * 8 * BLK, t + 1, 1)
            : L0args(S->fbt, 0, 0);    // K_62 second half = decoder layer0(d=0)
        lstm2_kernel<<<grid, 256, SMEM_BYTES>>>(g1, g2, 1);
        cur1 ^= 1; cur0 ^= 1; non ^= 1;
    }
    // decoder
    for (int d = 0; d < OUTL; d++) {
        GemmArgs g1 = L1args(0, 0, S->h1t);
        lstm2_kernel<<<grid, 256, SMEM_BYTES>>>(g1, g1, 0);
        cur1 ^= 1;
        linear_kernel<<<64, 256>>>(S->h1t, Wlin, blin, mean, stdv, S->fb, S->fbt, out, d);
        if (d + 1 < OUTL) {
            GemmArgs g0 = L0args(S->fbt, 0, 0);
            lstm2_kernel<<<grid, 256, SMEM_BYTES>>>(g0, g0, 0);
            cur0 ^= 1; non ^= 1;
        }
    }
}

// round 5
// speedup vs baseline: 1.0528x; 1.0528x over previous
#include <cuda_runtime.h>
#include <cuda_bf16.h>
#include <math.h>
#include <stdint.h>
#include <stddef.h>

#define TT 64
#define BB 512
#define FF 72
#define HH 1024
#define G4 4096
#define BLK 8192                 // elements per 128x64 bf16 tile (16KB)
#define NSTAGE 4
#define STAGE_BYTES 32768        // A tile 16KB + B tile 16KB
#define SMEM_BYTES (NSTAGE * STAGE_BYTES + 1024)
#define NTHR 512

// ---------------------------------------------------------------------------
// Scratch (device globals; allocations are forbidden)
// ---------------------------------------------------------------------------
struct __align__(16) Scratch {
    float bias0[G4], bias1[G4];
    float c0[HH * BB], c1[HH * BB];           // transposed: [unit][batch]
    float h1t[HH * BB];                       // fresh fp32 h1, transposed, for linear
    float fb[BB * FF];                        // feedback accumulator fp32
    __nv_bfloat16 xg[(TT - 1) * 4 * 2 * BLK]; // [t][m][2][BLK] swizzled
    __nv_bfloat16 W0[32 * 18 * BLK];          // [j][18][BLK] gate-interleaved rows
    __nv_bfloat16 W1[32 * 32 * BLK];
    __nv_bfloat16 h0s[2][4 * 16 * BLK];       // ping-pong state, swizzled
    __nv_bfloat16 h1s[2][4 * 16 * BLK];
    __nv_bfloat16 h0n[2][4 * 16 * BLK];       // fresh layer0 out, double-buffered
    __nv_bfloat16 fbt[4 * 2 * BLK];           // feedback, swizzled, padded
};
__device__ Scratch g_scratch;

// ---------------------------------------------------------------------------
// Helpers
// ---------------------------------------------------------------------------
__device__ __forceinline__ int swb(int byte) { return byte ^ ((byte >> 3) & 0x70); }
__device__ __forceinline__ int swofs(int r, int k) { return swb(r * 128 + k * 2) >> 1; }
__device__ __forceinline__ float sigmoidf_(float x) { return 1.0f / (1.0f + expf(-x)); }
__device__ __forceinline__ void cp16(uint32_t saddr, const void* gaddr) {
    asm volatile("cp.async.cg.shared.global [%0], [%1], 16;\n" :: "r"(saddr), "l"(gaddr));
}
__device__ __forceinline__ uint32_t smem_u32(const void* p) {
    return (uint32_t)__cvta_generic_to_shared(p);
}
__device__ __forceinline__ void ldsm4(uint32_t* r, uint32_t addr) {
    asm volatile("ldmatrix.sync.aligned.m8n8.x4.shared.b16 {%0,%1,%2,%3}, [%4];"
                 : "=r"(r[0]), "=r"(r[1]), "=r"(r[2]), "=r"(r[3]) : "r"(addr));
}
__device__ __forceinline__ void mma_bf16(float* c, const uint32_t* a, const uint32_t* b) {
    asm volatile(
        "mma.sync.aligned.m16n8k16.row.col.f32.bf16.bf16.f32 "
        "{%0,%1,%2,%3},{%4,%5,%6,%7},{%8,%9},{%0,%1,%2,%3};\n"
        : "+f"(c[0]), "+f"(c[1]), "+f"(c[2]), "+f"(c[3])
        : "r"(a[0]), "r"(a[1]), "r"(a[2]), "r"(a[3]), "r"(b[0]), "r"(b[1]));
}

// ---------------------------------------------------------------------------
// GEMM descriptor
// ---------------------------------------------------------------------------
struct GemmArgs {
    const __nv_bfloat16 *Aa, *Ab, *W;
    int Ca, Cb;
    const float* bias;
    const __nv_bfloat16* h_read;
    __nv_bfloat16* h_write;
    float* cbuf;                 // [unit][batch]
    __nv_bfloat16* hn_sw;        // fresh h, swizzled (nullable)
    float* hn_f32;               // fresh h, transposed fp32 (nullable)
    const int* lengths;
    int t, masked;
};

// ---------------------------------------------------------------------------
// Setup kernel 1: zero states + normalize/swizzle encoder inputs
// ---------------------------------------------------------------------------
__global__ void setup1_kernel(const float* __restrict__ u, const float* __restrict__ mean,
                              const float* __restrict__ stdv) {
    Scratch* S = &g_scratch;
    const int stride = gridDim.x * blockDim.x;
    const int t0 = blockIdx.x * blockDim.x + threadIdx.x;
    const __nv_bfloat16 z = __float2bfloat16(0.0f);
    for (int i = t0; i < 4 * 16 * BLK; i += stride) { S->h0s[0][i] = z; S->h1s[0][i] = z; }
    for (int i = t0; i < HH * BB; i += stride) { S->c0[i] = 0.0f; S->c1[i] = 0.0f; }
    for (int idx = t0; idx < (TT - 1) * 8 * BLK; idx += stride) {
        int e = idx & (BLK - 1);
        int i = (idx >> 13) & 1, m = (idx >> 14) & 3, t = idx >> 16;
        int r = e >> 6, k = e & 63;
        int b = m * 128 + r, col = i * 64 + k;
        float v = (col < FF) ? (u[((size_t)t * BB + b) * FF + col] - mean[col]) / stdv[col]
                             : 0.0f;
        S->xg[(size_t)(idx >> 13) * BLK + swofs(r, k)] = __float2bfloat16(v);
    }
}

// ---------------------------------------------------------------------------
// Setup kernel 2: weights (gate-interleaved SW128 tiles), biases, feedback init
// ---------------------------------------------------------------------------
__global__ void setup2_kernel(const float* __restrict__ u, const float* __restrict__ mean,
                              const float* __restrict__ stdv, const int* __restrict__ lengths,
                              const float* __restrict__ Wih0, const float* __restrict__ Whh0,
                              const float* __restrict__ Wih1, const float* __restrict__ Whh1,
                              const float* __restrict__ bi0, const float* __restrict__ bh0,
                              const float* __restrict__ bi1, const float* __restrict__ bh1) {
    Scratch* S = &g_scratch;
    const int stride = gridDim.x * blockDim.x;
    const int t0 = blockIdx.x * blockDim.x + threadIdx.x;
    // W0: 18 chunks (2 input-pad + 16 hh), gate-interleaved tile rows
    for (int idx = t0; idx < 32 * 18 * BLK; idx += stride) {
        int e = idx & (BLK - 1);
        int blk = idx >> 13;
        int i = blk % 18, j = blk / 18;
        int r = e >> 6, k = e & 63;
        int n = (r & 3) * 1024 + j * 32 + (r >> 2);
        float v;
        if (i < 2) {
            int col = i * 64 + k;
            v = (col < FF) ? Wih0[(size_t)n * FF + col] : 0.0f;
        } else {
            v = Whh0[(size_t)n * HH + (i - 2) * 64 + k];
        }
        S->W0[(size_t)blk * BLK + swofs(r, k)] = __float2bfloat16(v);
    }
    // W1: 32 chunks (16 ih + 16 hh)
    for (int idx = t0; idx < 32 * 32 * BLK; idx += stride) {
        int e = idx & (BLK - 1);
        int blk = idx >> 13;
        int i = blk & 31, j = blk >> 5;
        int r = e >> 6, k = e & 63;
        int n = (r & 3) * 1024 + j * 32 + (r >> 2);
        float v = (i < 16) ? Wih1[(size_t)n * HH + i * 64 + k]
                           : Whh1[(size_t)n * HH + (i - 16) * 64 + k];
        S->W1[(size_t)blk * BLK + swofs(r, k)] = __float2bfloat16(v);
    }
    for (int i = t0; i < G4; i += stride) {
        S->bias0[i] = bi0[i] + bh0[i];
        S->bias1[i] = bi1[i] + bh1[i];
    }
    // feedback = batch[lengths-1] (normalized); fp32 + swizzled bf16
    for (int idx = t0; idx < 4 * 2 * BLK; idx += stride) {
        int e = idx & (BLK - 1);
        int i = (idx >> 13) & 1, m = idx >> 14;
        int r = e >> 6, k = e & 63;
        int b = m * 128 + r, col = i * 64 + k;
        int tt = lengths[b] - 1;
        float v = (col < FF) ? (u[((size_t)tt * BB + b) * FF + col] - mean[col]) / stdv[col]
                             : 0.0f;
        S->fbt[(size_t)(idx >> 13) * BLK + swofs(r, k)] = __float2bfloat16(v);
    }
    for (int idx = t0; idx < BB * FF; idx += stride) {
        int b = idx / FF, n = idx % FF;
        int tt = lengths[b] - 1;
        S->fb[idx] = (u[((size_t)tt * BB + b) * FF + n] - mean[n]) / stdv[n];
    }
}

// ---------------------------------------------------------------------------
// Unified GEMM(+GEMM) + register LSTM epilogue kernel.
// CTA tile: 128 batch x 128 gate-interleaved cols. 512 threads:
// 16 warps = 4 M x 4 N. acc = [2][4][4] = 32 regs/thread.
// ---------------------------------------------------------------------------
__global__ void __launch_bounds__(NTHR, 1) lstm2_kernel(GemmArgs g1, GemmArgs g2, int has2) {
    extern __shared__ char raw_sm[];
    char* dsm = (char*)(((uintptr_t)raw_sm + 1023) & ~(uintptr_t)1023);
    const uint32_t dsm32 = smem_u32(dsm);

    const int tid = threadIdx.x;
    const int w = tid >> 5, lane = tid & 31;
    const int wm = w & 3, wn = w >> 2;          // 4 M-warps x 4 N-warps
    const int tig = lane & 3;
    const int bx = blockIdx.x, by = blockIdx.y;
    const int m0 = bx * 128, u0 = by * 32;
    const int CT1 = g1.Ca + g1.Cb;
    const int CT2 = has2 ? (g2.Ca + g2.Cb) : 0;
    const int CT = CT1 + CT2;

    const __nv_bfloat16* A1a = g1.Aa + (size_t)bx * g1.Ca * BLK;
    const __nv_bfloat16* A1b = g1.Ab + (size_t)bx * g1.Cb * BLK;
    const __nv_bfloat16* W1m = g1.W + (size_t)by * CT1 * BLK;
    const __nv_bfloat16* A2a = g2.Aa + (size_t)bx * g2.Ca * BLK;
    const __nv_bfloat16* A2b = g2.Ab + (size_t)bx * g2.Cb * BLK;
    const __nv_bfloat16* W2m = g2.W + (size_t)by * (g2.Ca + g2.Cb) * BLK;

    // ldmatrix lane patterns (tile-relative, pre-swizzle)
    const int rowA = wm * 32 + (lane & 15);
    const int cbA = (lane >> 4) * 16;
    const int rowB = wn * 32 + (lane & 7) + ((lane >> 4) & 1) * 8;
    const int cbB = ((lane >> 3) & 1) * 16;

    float acc[2][4][4];
#pragma unroll
    for (int a = 0; a < 2; a++)
#pragma unroll
        for (int b = 0; b < 4; b++)
#pragma unroll
            for (int c = 0; c < 4; c++) acc[a][b][c] = 0.0f;

    auto issue_chunk = [&](int j, int s) {
        const char* as;
        const char* ws;
        if (j < CT1) {
            as = (const char*)((j < g1.Ca) ? (A1a + (size_t)j * BLK)
                                           : (A1b + (size_t)(j - g1.Ca) * BLK));
            ws = (const char*)(W1m + (size_t)j * BLK);
        } else {
            int j2 = j - CT1;
            as = (const char*)((j2 < g2.Ca) ? (A2a + (size_t)j2 * BLK)
                                            : (A2b + (size_t)(j2 - g2.Ca) * BLK));
            ws = (const char*)(W2m + (size_t)j2 * BLK);
        }
        uint32_t da = dsm32 + s * STAGE_BYTES + tid * 16;
#pragma unroll
        for (int r = 0; r < 2; r++) cp16(da + r * 8192, as + tid * 16 + r * 8192);
        uint32_t db = da + 16384;
#pragma unroll
        for (int r = 0; r < 2; r++) cp16(db + r * 8192, ws + tid * 16 + r * 8192);
        asm volatile("cp.async.commit_group;\n" ::);
    };

    // register epilogue: shfl_xor(1) pairs gates {0,1} with {2,3}
    auto epilogue = [&](const GemmArgs& g) {
#pragma unroll
        for (int mt = 0; mt < 2; mt++)
#pragma unroll
            for (int nt = 0; nt < 4; nt++) {
                float d0 = acc[mt][nt][0], d1 = acc[mt][nt][1];
                float d2 = acc[mt][nt][2], d3 = acc[mt][nt][3];
                float p0 = __shfl_xor_sync(0xffffffffu, d0, 1);
                float p1 = __shfl_xor_sync(0xffffffffu, d1, 1);
                float p2 = __shfl_xor_sync(0xffffffffu, d2, 1);
                float p3 = __shfl_xor_sync(0xffffffffu, d3, 1);
                acc[mt][nt][0] = 0.0f; acc[mt][nt][1] = 0.0f;
                acc[mt][nt][2] = 0.0f; acc[mt][nt][3] = 0.0f;
                int u = u0 + wn * 8 + 2 * nt + (tig >> 1);
                int b = m0 + wm * 32 + mt * 16 + (lane >> 2) + ((tig & 1) ? 8 : 0);
                float I, F, G, O;
                if (!(tig & 1)) { I = d0; F = d1; G = p0; O = p1; }
                else            { G = d2; O = d3; I = p2; F = p3; }
                I += g.bias[u]; F += g.bias[1024 + u];
                G += g.bias[2048 + u]; O += g.bias[3072 + u];
                float cp = g.cbuf[(size_t)u * BB + b];
                float cn = sigmoidf_(F) * cp + sigmoidf_(I) * tanhf(G);
                float hn = sigmoidf_(O) * tanhf(cn);
                __nv_bfloat16 hb = __float2bfloat16(hn);
                size_t hidx = (size_t)((b >> 7) * 16 + (u >> 6)) * BLK + swofs(b & 127, u & 63);
                bool upd = !g.masked || (g.t < g.lengths[b] - 1);
                if (upd) {
                    g.cbuf[(size_t)u * BB + b] = cn;
                    g.h_write[hidx] = hb;
                } else {
                    g.h_write[hidx] = g.h_read[hidx];
                }
                if (g.hn_sw) g.hn_sw[hidx] = hb;
                if (g.hn_f32) g.hn_f32[(size_t)u * BB + b] = hn;
            }
    };

#pragma unroll
    for (int j = 0; j < NSTAGE - 1; j++) issue_chunk(j, j);

    for (int i = 0; i < CT; i++) {
        const int s = i & (NSTAGE - 1);
        const int rem = CT - 1 - i;
        if (rem >= 2)      asm volatile("cp.async.wait_group 2;\n" ::);
        else if (rem == 1) asm volatile("cp.async.wait_group 1;\n" ::);
        else               asm volatile("cp.async.wait_group 0;\n" ::);
        __syncthreads();
        const int j = i + NSTAGE - 1;
        if (j < CT) issue_chunk(j, j & (NSTAGE - 1));

        const uint32_t Ab = dsm32 + s * STAGE_BYTES;
        const uint32_t Bb = Ab + 16384;
#pragma unroll
        for (int ks = 0; ks < 4; ks++) {
            uint32_t afr[2][4];
#pragma unroll
            for (int mt = 0; mt < 2; mt++)
                ldsm4(afr[mt], Ab + swb((rowA + mt * 16) * 128 + ks * 32 + cbA));
            uint32_t bfr[4][2];
#pragma unroll
            for (int pr = 0; pr < 2; pr++) {
                uint32_t r4[4];
                ldsm4(r4, Bb + swb((rowB + pr * 16) * 128 + ks * 32 + cbB));
                bfr[2 * pr][0] = r4[0]; bfr[2 * pr][1] = r4[1];
                bfr[2 * pr + 1][0] = r4[2]; bfr[2 * pr + 1][1] = r4[3];
            }
#pragma unroll
            for (int mt = 0; mt < 2; mt++)
#pragma unroll
                for (int nt = 0; nt < 4; nt++) mma_bf16(acc[mt][nt], afr[mt], bfr[nt]);
        }

        if (i == CT1 - 1) epilogue(g1);
        if (has2 && i == CT - 1) epilogue(g2);
    }
}

// ---------------------------------------------------------------------------
// Decoder linear readout: 8 batches per CTA, Wlin streamed once per CTA.
// h1t is [unit][batch] fp32.
// ---------------------------------------------------------------------------
__global__ void __launch_bounds__(256) linear_kernel(
    const float* __restrict__ h1t, const float* __restrict__ Wlin,
    const float* __restrict__ blin, const float* __restrict__ mean,
    const float* __restrict__ stdv, float* __restrict__ fb,
    __nv_bfloat16* __restrict__ fbt, float* __restrict__ out, int step) {
    __shared__ float hs[HH * 9];   // [u][8] padded to 9
    const int b0 = blockIdx.x * 8;
    const int tid = threadIdx.x;
    for (int idx = tid; idx < HH * 8; idx += 256) {
        int u = idx >> 3, bl = idx & 7;
        hs[u * 9 + bl] = h1t[(size_t)u * BB + b0 + bl];
    }
    __syncthreads();
    const int w = tid >> 5, lane = tid & 31;
#pragma unroll
    for (int jj = 0; jj < 9; jj++) {
        int n = w + 8 * jj;   // 0..71
        float a[8];
#pragma unroll
        for (int bl = 0; bl < 8; bl++) a[bl] = 0.0f;
        for (int u = lane; u < HH; u += 32) {
            float wv = Wlin[(size_t)n * HH + u];
#pragma unroll
            for (int bl = 0; bl < 8; bl++) a[bl] += wv * hs[u * 9 + bl];
        }
#pragma unroll
        for (int bl = 0; bl < 8; bl++)
#pragma unroll
            for (int off = 16; off; off >>= 1)
                a[bl] += __shfl_xor_sync(0xffffffffu, a[bl], off);
        if (lane == 0) {
#pragma unroll
            for (int bl = 0; bl < 8; bl++) {
                int b = b0 + bl;
                float f2 = fb[b * FF + n] + a[bl] + blin[n];
                fb[b * FF + n] = f2;
                fbt[(size_t)((b >> 7) * 2 + (n >> 6)) * BLK + swofs(b & 127, n & 63)] =
                    __float2bfloat16(f2);
                out[((size_t)step * BB + b) * FF + n] = f2 * stdv[n] + mean[n];
            }
        }
    }
}

// ---------------------------------------------------------------------------
// Host orchestration
// ---------------------------------------------------------------------------
extern "C" void kernel_launch(void* const* d_in, const int* in_sizes, int n_in,
                              void* d_out, int out_size) {
    int off = (n_in >= 15) ? 1 : 0;
    const float* batch_u = (const float*)d_in[0];
    const int* lengths   = (const int*)d_in[1];
    const float* mean    = (const float*)d_in[2 + off];
    const float* stdv    = (const float*)d_in[3 + off];
    const float* Wih0    = (const float*)d_in[4 + off];
    const float* Whh0    = (const float*)d_in[5 + off];
    const float* bih0    = (const float*)d_in[6 + off];
    const float* bhh0    = (const float*)d_in[7 + off];
    const float* Wih1    = (const float*)d_in[8 + off];
    const float* Whh1    = (const float*)d_in[9 + off];
    const float* bih1    = (const float*)d_in[10 + off];
    const float* bhh1    = (const float*)d_in[11 + off];
    const float* Wlin    = (const float*)d_in[12 + off];
    const float* blin    = (const float*)d_in[13 + off];
    float* out = (float*)d_out;
    const int OUTL = out_size / (BB * FF);

    Scratch* S = nullptr;
    cudaGetSymbolAddress((void**)&S, g_scratch);
    cudaFuncSetAttribute(lstm2_kernel, cudaFuncAttributeMaxDynamicSharedMemorySize,
                         SMEM_BYTES);

    // launches 1-2: setup (includes state zeroing + feedback init)
    setup1_kernel<<<1024, 256>>>(batch_u, mean, stdv);
    setup2_kernel<<<1024, 256>>>(batch_u, mean, stdv, lengths, Wih0, Whh0, Wih1, Whh1,
                                 bih0, bhh0, bih1, bhh1);

    dim3 grid(4, 32);
    int cur0 = 0, cur1 = 0, non = 0;

    auto L0args = [&](const __nv_bfloat16* Aa, int t, int masked) {
        GemmArgs g;
        g.Aa = Aa; g.Ca = 2; g.Ab = S->h0s[cur0]; g.Cb = 16;
        g.W = S->W0; g.bias = S->bias0;
        g.h_read = S->h0s[cur0]; g.h_write = S->h0s[cur0 ^ 1];
        g.cbuf = S->c0; g.hn_sw = S->h0n[non ^ 1]; g.hn_f32 = nullptr;
        g.lengths = lengths; g.t = t; g.masked = masked;
        return g;
    };
    auto L1args = [&](int t, int masked, float* hnf) {
        GemmArgs g;
        g.Aa = S->h0n[non]; g.Ca = 16; g.Ab = S->h1s[cur1]; g.Cb = 16;
        g.W = S->W1; g.bias = S->bias1;
        g.h_read = S->h1s[cur1]; g.h_write = S->h1s[cur1 ^ 1];
        g.cbuf = S->c1; g.hn_sw = nullptr; g.hn_f32 = hnf;
        g.lengths = lengths; g.t = t; g.masked = masked;
        return g;
    };

    // launch 3: E0 = layer0(t=0)
    {
        GemmArgs g = L0args(S->xg, 0, 1);
        lstm2_kernel<<<grid, NTHR, SMEM_BYTES>>>(g, g, 0);
        cur0 ^= 1; non ^= 1;
    }
    // launches 4..66: merged K_t = layer1(t) + layer0(t+1)  (t=0..62)
    for (int t = 0; t < TT - 1; t++) {
        GemmArgs g1 = L1args(t, 1, nullptr);
        GemmArgs g2 = (t < TT - 2)
            ? L0args(S->xg + (size_t)(t + 1) * 8 * BLK, t + 1, 1)
            : L0args(S->fbt, 0, 0);    // last merge: decoder layer0(d=0)
        lstm2_kernel<<<grid, NTHR, SMEM_BYTES>>>(g1, g2, 1);
        cur1 ^= 1; cur0 ^= 1; non ^= 1;
    }
    // decoder
    for (int d = 0; d < OUTL; d++) {
        GemmArgs g1 = L1args(0, 0, S->h1t);
        lstm2_kernel<<<grid, NTHR, SMEM_BYTES>>>(g1, g1, 0);
        cur1 ^= 1;
        linear_kernel<<<64, 256>>>(S->h1t, Wlin, blin, mean, stdv, S->fb, S->fbt, out, d);
        if (d + 1 < OUTL) {
            GemmArgs g0 = L0args(S->fbt, 0, 0);
            lstm2_kernel<<<grid, NTHR, SMEM_BYTES>>>(g0, g0, 0);
            cur0 ^= 1; non ^= 1;
        }
    }
}

// round 6
// speedup vs baseline: 1.3815x; 1.3122x over previous
#include <cuda_runtime.h>
#include <cuda_bf16.h>
#include <math.h>
#include <stdint.h>
#include <stddef.h>

#define TT 64
#define BB 512
#define FF 72
#define HH 1024
#define G4 4096
#define BLK 8192                 // A-tile elements (128x64 bf16 = 16KB)
#define WBLK 4096                // W-tile elements (64x64 bf16 = 8KB)
#define NSTAGE 4
#define STAGE_B 24576            // A 16KB + B 8KB
#define SMEM_BYTES (NSTAGE * STAGE_B + 1024)   // 99328
#define NTHR 256
#define GRID 256                 // 4 bx * 64 by

// ---------------------------------------------------------------------------
// Scratch + barrier state (device globals; allocations forbidden)
// ---------------------------------------------------------------------------
struct __align__(16) Scratch {
    float bias0[G4], bias1[G4];
    float c0[HH * BB], c1[HH * BB];           // [unit][batch]
    float h1t[HH * BB];                       // fresh fp32 h1 [unit][batch]
    float fb[BB * FF];
    __nv_bfloat16 xg[(TT - 1) * 4 * 2 * BLK]; // [t][m][2][BLK] swizzled
    __nv_bfloat16 W0[64 * 18 * WBLK];         // [by][18][WBLK] 64-row gate-interleaved
    __nv_bfloat16 W1[64 * 32 * WBLK];
    __nv_bfloat16 h0s[2][4 * 16 * BLK];
    __nv_bfloat16 h1s[2][4 * 16 * BLK];
    __nv_bfloat16 h0n[2][4 * 16 * BLK];
    __nv_bfloat16 fbt[4 * 2 * BLK];
};
__device__ Scratch g_scratch;
__device__ unsigned g_arr;
__device__ unsigned g_rel;

// ---------------------------------------------------------------------------
// Helpers
// ---------------------------------------------------------------------------
__device__ __forceinline__ int swb(int byte) { return byte ^ ((byte >> 3) & 0x70); }
__device__ __forceinline__ int swofs(int r, int k) { return swb(r * 128 + k * 2) >> 1; }
__device__ __forceinline__ float sigmoidf_(float x) { return 1.0f / (1.0f + expf(-x)); }
__device__ __forceinline__ void cp16(uint32_t saddr, const void* gaddr) {
    asm volatile("cp.async.cg.shared.global [%0], [%1], 16;\n" :: "r"(saddr), "l"(gaddr));
}
__device__ __forceinline__ uint32_t smem_u32(const void* p) {
    return (uint32_t)__cvta_generic_to_shared(p);
}
__device__ __forceinline__ void ldsm4(uint32_t* r, uint32_t addr) {
    asm volatile("ldmatrix.sync.aligned.m8n8.x4.shared.b16 {%0,%1,%2,%3}, [%4];"
                 : "=r"(r[0]), "=r"(r[1]), "=r"(r[2]), "=r"(r[3]) : "r"(addr));
}
__device__ __forceinline__ void mma_bf16(float* c, const uint32_t* a, const uint32_t* b) {
    asm volatile(
        "mma.sync.aligned.m16n8k16.row.col.f32.bf16.bf16.f32 "
        "{%0,%1,%2,%3},{%4,%5,%6,%7},{%8,%9},{%0,%1,%2,%3};\n"
        : "+f"(c[0]), "+f"(c[1]), "+f"(c[2]), "+f"(c[3])
        : "r"(a[0]), "r"(a[1]), "r"(a[2]), "r"(a[3]), "r"(b[0]), "r"(b[1]));
}

// Grid-wide barrier: sense-free monotonic release counter.
__device__ __forceinline__ void gridbar(unsigned& epoch) {
    __syncthreads();
    if (threadIdx.x == 0) {
        __threadfence();
        unsigned prev = atomicAdd(&g_arr, 1u);
        if (prev == gridDim.x - 1) {
            g_arr = 0u;
            __threadfence();
            atomicExch(&g_rel, epoch + 1u);
        } else {
            while (*(volatile unsigned*)&g_rel < epoch + 1u) __nanosleep(64);
        }
        __threadfence();
    }
    __syncthreads();
    epoch++;
}

// ---------------------------------------------------------------------------
// GEMM phase descriptor
// ---------------------------------------------------------------------------
struct GP {
    const __nv_bfloat16 *Aa, *Ab, *W;
    int Ca, Cb;
    const float* bias;
    const __nv_bfloat16* h_read;
    __nv_bfloat16* h_write;
    float* cbuf;
    __nv_bfloat16* hn_sw;
    float* hn_f32;
    const int* lengths;
    int t, masked;
};

// ---------------------------------------------------------------------------
// Setup kernels
// ---------------------------------------------------------------------------
__global__ void setup1_kernel(const float* __restrict__ u, const float* __restrict__ mean,
                              const float* __restrict__ stdv) {
    Scratch* S = &g_scratch;
    const int stride = gridDim.x * blockDim.x;
    const int t0 = blockIdx.x * blockDim.x + threadIdx.x;
    if (t0 == 0) { g_arr = 0u; g_rel = 0u; }
    const __nv_bfloat16 z = __float2bfloat16(0.0f);
    for (int i = t0; i < 4 * 16 * BLK; i += stride) { S->h0s[0][i] = z; S->h1s[0][i] = z; }
    for (int i = t0; i < HH * BB; i += stride) { S->c0[i] = 0.0f; S->c1[i] = 0.0f; }
    for (int idx = t0; idx < (TT - 1) * 8 * BLK; idx += stride) {
        int e = idx & (BLK - 1);
        int i = (idx >> 13) & 1, m = (idx >> 14) & 3, t = idx >> 16;
        int r = e >> 6, k = e & 63;
        int b = m * 128 + r, col = i * 64 + k;
        float v = (col < FF) ? (u[((size_t)t * BB + b) * FF + col] - mean[col]) / stdv[col]
                             : 0.0f;
        S->xg[(size_t)(idx >> 13) * BLK + swofs(r, k)] = __float2bfloat16(v);
    }
}

__global__ void setup2_kernel(const float* __restrict__ u, const float* __restrict__ mean,
                              const float* __restrict__ stdv, const int* __restrict__ lengths,
                              const float* __restrict__ Wih0, const float* __restrict__ Whh0,
                              const float* __restrict__ Wih1, const float* __restrict__ Whh1,
                              const float* __restrict__ bi0, const float* __restrict__ bh0,
                              const float* __restrict__ bi1, const float* __restrict__ bh1) {
    Scratch* S = &g_scratch;
    const int stride = gridDim.x * blockDim.x;
    const int t0 = blockIdx.x * blockDim.x + threadIdx.x;
    // W0: [by 0..63][chunk 0..17], tile rows n = gate*1024 + by*16 + unit
    for (int idx = t0; idx < 64 * 18 * WBLK; idx += stride) {
        int e = idx & (WBLK - 1);
        int blk = idx >> 12;
        int i = blk % 18, by = blk / 18;
        int r = e >> 6, k = e & 63;
        int n = (r & 3) * 1024 + by * 16 + (r >> 2);
        float v;
        if (i < 2) {
            int col = i * 64 + k;
            v = (col < FF) ? Wih0[(size_t)n * FF + col] : 0.0f;
        } else {
            v = Whh0[(size_t)n * HH + (i - 2) * 64 + k];
        }
        S->W0[(size_t)blk * WBLK + swofs(r, k)] = __float2bfloat16(v);
    }
    // W1: [by][chunk 0..31]
    for (int idx = t0; idx < 64 * 32 * WBLK; idx += stride) {
        int e = idx & (WBLK - 1);
        int blk = idx >> 12;
        int i = blk & 31, by = blk >> 5;
        int r = e >> 6, k = e & 63;
        int n = (r & 3) * 1024 + by * 16 + (r >> 2);
        float v = (i < 16) ? Wih1[(size_t)n * HH + i * 64 + k]
                           : Whh1[(size_t)n * HH + (i - 16) * 64 + k];
        S->W1[(size_t)blk * WBLK + swofs(r, k)] = __float2bfloat16(v);
    }
    for (int i = t0; i < G4; i += stride) {
        S->bias0[i] = bi0[i] + bh0[i];
        S->bias1[i] = bi1[i] + bh1[i];
    }
    for (int idx = t0; idx < 4 * 2 * BLK; idx += stride) {
        int e = idx & (BLK - 1);
        int i = (idx >> 13) & 1, m = idx >> 14;
        int r = e >> 6, k = e & 63;
        int b = m * 128 + r, col = i * 64 + k;
        int tt = lengths[b] - 1;
        float v = (col < FF) ? (u[((size_t)tt * BB + b) * FF + col] - mean[col]) / stdv[col]
                             : 0.0f;
        S->fbt[(size_t)(idx >> 13) * BLK + swofs(r, k)] = __float2bfloat16(v);
    }
    for (int idx = t0; idx < BB * FF; idx += stride) {
        int b = idx / FF, n = idx % FF;
        int tt = lengths[b] - 1;
        S->fb[idx] = (u[((size_t)tt * BB + b) * FF + n] - mean[n]) / stdv[n];
    }
}

// ---------------------------------------------------------------------------
// GEMM(+GEMM) with register LSTM epilogue. CTA tile 128x64 (batch x gatecols),
// 8 warps = 4M x 2N, acc[2][4][4].
// ---------------------------------------------------------------------------
__device__ __forceinline__ void do_gemm(const GP& g1, const GP& g2, int has2,
                                        uint32_t dsm32, int bx, int by) {
    const int tid = threadIdx.x;
    const int w = tid >> 5, lane = tid & 31;
    const int wm = w & 3, wn = w >> 2;     // 4 M x 2 N
    const int tig = lane & 3;
    const int m0 = bx * 128;
    const int u00 = by * 16;
    const int CT1 = g1.Ca + g1.Cb;
    const int CT = CT1 + (has2 ? (g2.Ca + g2.Cb) : 0);

    const __nv_bfloat16* A1a = g1.Aa + (size_t)bx * g1.Ca * BLK;
    const __nv_bfloat16* A1b = g1.Ab + (size_t)bx * g1.Cb * BLK;
    const __nv_bfloat16* W1m = g1.W + (size_t)by * CT1 * WBLK;
    const __nv_bfloat16* A2a = g2.Aa + (size_t)bx * g2.Ca * BLK;
    const __nv_bfloat16* A2b = g2.Ab + (size_t)bx * g2.Cb * BLK;
    const __nv_bfloat16* W2m = g2.W + (size_t)by * (g2.Ca + g2.Cb) * WBLK;

    const int rowA = wm * 32 + (lane & 15);
    const int cbA = (lane >> 4) * 16;
    const int rowB = wn * 32 + (lane & 7) + ((lane >> 4) & 1) * 8;
    const int cbB = ((lane >> 3) & 1) * 16;

    float acc[2][4][4];
#pragma unroll
    for (int a = 0; a < 2; a++)
#pragma unroll
        for (int b = 0; b < 4; b++)
#pragma unroll
            for (int c = 0; c < 4; c++) acc[a][b][c] = 0.0f;

    auto issue_chunk = [&](int j, int s) {
        const char* as;
        const char* ws;
        if (j < CT1) {
            as = (const char*)((j < g1.Ca) ? (A1a + (size_t)j * BLK)
                                           : (A1b + (size_t)(j - g1.Ca) * BLK));
            ws = (const char*)(W1m + (size_t)j * WBLK);
        } else {
            int j2 = j - CT1;
            as = (const char*)((j2 < g2.Ca) ? (A2a + (size_t)j2 * BLK)
                                            : (A2b + (size_t)(j2 - g2.Ca) * BLK));
            ws = (const char*)(W2m + (size_t)j2 * WBLK);
        }
        uint32_t da = dsm32 + s * STAGE_B + tid * 16;
#pragma unroll
        for (int r = 0; r < 4; r++) cp16(da + r * 4096, as + tid * 16 + r * 4096);
        uint32_t db = da + 16384;
#pragma unroll
        for (int r = 0; r < 2; r++) cp16(db + r * 4096, ws + tid * 16 + r * 4096);
        asm volatile("cp.async.commit_group;\n" ::);
    };

    auto epilogue = [&](const GP& g) {
#pragma unroll
        for (int mt = 0; mt < 2; mt++)
#pragma unroll
            for (int nt = 0; nt < 4; nt++) {
                float d0 = acc[mt][nt][0], d1 = acc[mt][nt][1];
                float d2 = acc[mt][nt][2], d3 = acc[mt][nt][3];
                float p0 = __shfl_xor_sync(0xffffffffu, d0, 1);
                float p1 = __shfl_xor_sync(0xffffffffu, d1, 1);
                float p2 = __shfl_xor_sync(0xffffffffu, d2, 1);
                float p3 = __shfl_xor_sync(0xffffffffu, d3, 1);
                acc[mt][nt][0] = 0.0f; acc[mt][nt][1] = 0.0f;
                acc[mt][nt][2] = 0.0f; acc[mt][nt][3] = 0.0f;
                int u = u00 + wn * 8 + 2 * nt + (tig >> 1);
                int b = m0 + wm * 32 + mt * 16 + (lane >> 2) + ((tig & 1) ? 8 : 0);
                float I, F, G, O;
                if (!(tig & 1)) { I = d0; F = d1; G = p0; O = p1; }
                else            { G = d2; O = d3; I = p2; F = p3; }
                I += g.bias[u]; F += g.bias[1024 + u];
                G += g.bias[2048 + u]; O += g.bias[3072 + u];
                float cp = g.cbuf[(size_t)u * BB + b];
                float cn = sigmoidf_(F) * cp + sigmoidf_(I) * tanhf(G);
                float hn = sigmoidf_(O) * tanhf(cn);
                __nv_bfloat16 hb = __float2bfloat16(hn);
                size_t hidx = (size_t)((b >> 7) * 16 + (u >> 6)) * BLK + swofs(b & 127, u & 63);
                bool upd = !g.masked || (g.t < g.lengths[b] - 1);
                if (upd) {
                    g.cbuf[(size_t)u * BB + b] = cn;
                    g.h_write[hidx] = hb;
                } else {
                    g.h_write[hidx] = g.h_read[hidx];
                }
                if (g.hn_sw) g.hn_sw[hidx] = hb;
                if (g.hn_f32) g.hn_f32[(size_t)u * BB + b] = hn;
            }
    };

#pragma unroll
    for (int j = 0; j < NSTAGE - 1; j++) issue_chunk(j, j);

    for (int i = 0; i < CT; i++) {
        const int s = i & (NSTAGE - 1);
        const int rem = CT - 1 - i;
        if (rem >= 2)      asm volatile("cp.async.wait_group 2;\n" ::);
        else if (rem == 1) asm volatile("cp.async.wait_group 1;\n" ::);
        else               asm volatile("cp.async.wait_group 0;\n" ::);
        __syncthreads();
        const int j = i + NSTAGE - 1;
        if (j < CT) issue_chunk(j, j & (NSTAGE - 1));

        const uint32_t Ab = dsm32 + s * STAGE_B;
        const uint32_t Bb = Ab + 16384;
#pragma unroll
        for (int ks = 0; ks < 4; ks++) {
            uint32_t afr[2][4];
#pragma unroll
            for (int mt = 0; mt < 2; mt++)
                ldsm4(afr[mt], Ab + swb((rowA + mt * 16) * 128 + ks * 32 + cbA));
            uint32_t bfr[4][2];
#pragma unroll
            for (int pr = 0; pr < 2; pr++) {
                uint32_t r4[4];
                ldsm4(r4, Bb + swb((rowB + pr * 16) * 128 + ks * 32 + cbB));
                bfr[2 * pr][0] = r4[0]; bfr[2 * pr][1] = r4[1];
                bfr[2 * pr + 1][0] = r4[2]; bfr[2 * pr + 1][1] = r4[3];
            }
#pragma unroll
            for (int mt = 0; mt < 2; mt++)
#pragma unroll
                for (int nt = 0; nt < 4; nt++) mma_bf16(acc[mt][nt], afr[mt], bfr[nt]);
        }

        if (i == CT1 - 1) epilogue(g1);
        if (has2 && i == CT - 1) epilogue(g2);
    }
    __syncthreads();   // all reads of last stages done before next phase reuses smem
}

// ---------------------------------------------------------------------------
// Linear phase: CTA (bx,by) -> batches by*8..+8, outputs bx*18..+18.
// ---------------------------------------------------------------------------
__device__ __forceinline__ void do_linear(char* dsm, int bx, int by, int step,
                                          const float* Wlin, const float* blin,
                                          const float* mean, const float* stdv,
                                          float* out) {
    Scratch* S = &g_scratch;
    float* hs = (float*)dsm;   // [1024][9]
    const int b0 = by * 8;
    const int tid = threadIdx.x;
    for (int idx = tid; idx < HH * 8; idx += NTHR) {
        int u = idx >> 3, bl = idx & 7;
        hs[u * 9 + bl] = S->h1t[(size_t)u * BB + b0 + bl];
    }
    __syncthreads();
    const int w = tid >> 5, lane = tid & 31;
#pragma unroll
    for (int jj = 0; jj < 3; jj++) {
        int nl = w + 8 * jj;
        if (nl >= 18) break;
        int n = bx * 18 + nl;
        float a[8];
#pragma unroll
        for (int bl = 0; bl < 8; bl++) a[bl] = 0.0f;
        for (int u = lane; u < HH; u += 32) {
            float wv = Wlin[(size_t)n * HH + u];
#pragma unroll
            for (int bl = 0; bl < 8; bl++) a[bl] += wv * hs[u * 9 + bl];
        }
#pragma unroll
        for (int bl = 0; bl < 8; bl++)
#pragma unroll
            for (int off = 16; off; off >>= 1)
                a[bl] += __shfl_xor_sync(0xffffffffu, a[bl], off);
        if (lane == 0) {
#pragma unroll
            for (int bl = 0; bl < 8; bl++) {
                int b = b0 + bl;
                float f2 = S->fb[b * FF + n] + a[bl] + blin[n];
                S->fb[b * FF + n] = f2;
                S->fbt[(size_t)((b >> 7) * 2 + (n >> 6)) * BLK + swofs(b & 127, n & 63)] =
                    __float2bfloat16(f2);
                out[((size_t)step * BB + b) * FF + n] = f2 * stdv[n] + mean[n];
            }
        }
    }
    __syncthreads();
}

// ---------------------------------------------------------------------------
// Persistent kernel: entire recurrence with in-kernel grid barriers.
// ---------------------------------------------------------------------------
__global__ void __launch_bounds__(NTHR, 2) persist_kernel(
    const int* __restrict__ lengths, const float* __restrict__ Wlin,
    const float* __restrict__ blin, const float* __restrict__ mean,
    const float* __restrict__ stdv, float* __restrict__ out, int OUTL) {
    extern __shared__ char raw_sm[];
    char* dsm = (char*)(((uintptr_t)raw_sm + 1023) & ~(uintptr_t)1023);
    const uint32_t dsm32 = smem_u32(dsm);
    Scratch* S = &g_scratch;
    const int bx = blockIdx.x & 3, by = blockIdx.x >> 2;
    unsigned epoch = 0;
    int cur0 = 0, cur1 = 0, non = 0;

    auto L0args = [&](const __nv_bfloat16* Aa, int t, int masked) {
        GP g;
        g.Aa = Aa; g.Ca = 2; g.Ab = S->h0s[cur0]; g.Cb = 16;
        g.W = S->W0; g.bias = S->bias0;
        g.h_read = S->h0s[cur0]; g.h_write = S->h0s[cur0 ^ 1];
        g.cbuf = S->c0; g.hn_sw = S->h0n[non ^ 1]; g.hn_f32 = nullptr;
        g.lengths = lengths; g.t = t; g.masked = masked;
        return g;
    };
    auto L1args = [&](int t, int masked, float* hnf) {
        GP g;
        g.Aa = S->h0n[non]; g.Ca = 16; g.Ab = S->h1s[cur1]; g.Cb = 16;
        g.W = S->W1; g.bias = S->bias1;
        g.h_read = S->h1s[cur1]; g.h_write = S->h1s[cur1 ^ 1];
        g.cbuf = S->c1; g.hn_sw = nullptr; g.hn_f32 = hnf;
        g.lengths = lengths; g.t = t; g.masked = masked;
        return g;
    };

    // E0: layer0(t=0)
    {
        GP g = L0args(S->xg, 0, 1);
        do_gemm(g, g, 0, dsm32, bx, by);
    }
    gridbar(epoch); cur0 ^= 1; non ^= 1;

    // encoder merged: layer1(t) + layer0(t+1)
    for (int t = 0; t < TT - 1; t++) {
        GP g1 = L1args(t, 1, nullptr);
        GP g2 = (t < TT - 2) ? L0args(S->xg + (size_t)(t + 1) * 8 * BLK, t + 1, 1)
                             : L0args(S->fbt, 0, 0);
        do_gemm(g1, g2, 1, dsm32, bx, by);
        gridbar(epoch); cur1 ^= 1; cur0 ^= 1; non ^= 1;
    }

    // decoder
    for (int d = 0; d < OUTL; d++) {
        GP g1 = L1args(0, 0, S->h1t);
        do_gemm(g1, g1, 0, dsm32, bx, by);
        gridbar(epoch); cur1 ^= 1;
        do_linear(dsm, bx, by, d, Wlin, blin, mean, stdv, out);
        gridbar(epoch);
        if (d + 1 < OUTL) {
            GP g0 = L0args(S->fbt, 0, 0);
            do_gemm(g0, g0, 0, dsm32, bx, by);
            gridbar(epoch); cur0 ^= 1; non ^= 1;
        }
    }
}

// ---------------------------------------------------------------------------
// Host orchestration
// ---------------------------------------------------------------------------
extern "C" void kernel_launch(void* const* d_in, const int* in_sizes, int n_in,
                              void* d_out, int out_size) {
    int off = (n_in >= 15) ? 1 : 0;
    const float* batch_u = (const float*)d_in[0];
    const int* lengths   = (const int*)d_in[1];
    const float* mean    = (const float*)d_in[2 + off];
    const float* stdv    = (const float*)d_in[3 + off];
    const float* Wih0    = (const float*)d_in[4 + off];
    const float* Whh0    = (const float*)d_in[5 + off];
    const float* bih0    = (const float*)d_in[6 + off];
    const float* bhh0    = (const float*)d_in[7 + off];
    const float* Wih1    = (const float*)d_in[8 + off];
    const float* Whh1    = (const float*)d_in[9 + off];
    const float* bih1    = (const float*)d_in[10 + off];
    const float* bhh1    = (const float*)d_in[11 + off];
    const float* Wlin    = (const float*)d_in[12 + off];
    const float* blin    = (const float*)d_in[13 + off];
    float* out = (float*)d_out;
    const int OUTL = out_size / (BB * FF);

    cudaFuncSetAttribute(persist_kernel, cudaFuncAttributeMaxDynamicSharedMemorySize,
                         SMEM_BYTES);

    setup1_kernel<<<1024, 256>>>(batch_u, mean, stdv);
    setup2_kernel<<<1024, 256>>>(batch_u, mean, stdv, lengths, Wih0, Whh0, Wih1, Whh1,
                                 bih0, bhh0, bih1, bhh1);
    persist_kernel<<<GRID, NTHR, SMEM_BYTES>>>(lengths, Wlin, blin, mean, stdv, out, OUTL);
}